// round 7
// baseline (speedup 1.0000x reference)
#include <cuda_runtime.h>
#include <math.h>
#include <stdint.h>

// Problem constants
#define BB    16
#define CC    64
#define HWSZ  4096
#define NPIX  65536
#define KK    1024
#define DD    64
#define NEL   4194304
#define GATHER_BLOCKS 4096     // NEL / 4 / 256
#define NSLOT 8

// Device scratch
__device__ __align__(16) int      g_idx[NPIX];
__device__ float                  g_counts[KK];
__device__ __align__(8)  float2   g_cnsc[KK];        // (cn_exact, 1/sc)
__device__ __align__(16) uint32_t g_qc[KK * 16];     // int8-packed codebook
__device__ float                  g_part[GATHER_BLOCKS];
__device__ int                    g_l1cmax_i;        // bits of max L1(c)  (monotonic)
__device__ int                    g_cmaxmax_i;       // bits of max cmax   (monotonic)

// ---------------------------------------------------------------------------
// Kernel 1: prep — exact cn, int8 codebook, scale/L1 stats, zero histogram
// ---------------------------------------------------------------------------
__global__ void prep_kernel(const float* __restrict__ cb) {
    int k = blockIdx.x * 256 + threadIdx.x;
    if (k >= KK) return;
    float xr[DD];
    float s = 0.f, cmax = 0.f, l1 = 0.f;
    #pragma unroll
    for (int d = 0; d < DD; d++) {
        float v = cb[k * DD + d];
        xr[d] = v;
        s = __fadd_rn(s, __fmul_rn(v, v));   // reference-exact cn
        float a = fabsf(v);
        cmax = fmaxf(cmax, a);
        l1  += a;
    }
    float sc = 126.f / fmaxf(cmax, 1e-30f);
    #pragma unroll
    for (int w = 0; w < 16; w++) {
        uint32_t pk = 0;
        #pragma unroll
        for (int j = 0; j < 4; j++) {
            int q = __float2int_rn(xr[w * 4 + j] * sc);
            pk |= ((uint32_t)(q & 0xFF)) << (j * 8);
        }
        g_qc[k * 16 + w] = pk;
    }
    g_cnsc[k]   = make_float2(s, 1.f / sc);
    g_counts[k] = 0.f;
    atomicMax(&g_l1cmax_i,  __float_as_int(l1));      // positive floats: int order ok
    atomicMax(&g_cmaxmax_i, __float_as_int(cmax));
}

// ---------------------------------------------------------------------------
// Kernel 2: dp4a coarse scan + slot filter + exact-fp32 refine argmin
// 128 threads = 128 pixels per block; qc streamed warp-uniform via __ldg.
// ---------------------------------------------------------------------------
__global__ void __launch_bounds__(128)
argmin_kernel(const float* __restrict__ in, const float* __restrict__ cb) {
    __shared__ float  xs[DD * 128];     // 32KB: xs[d][p]
    __shared__ float2 cnsc[KK];         // 8KB

    const int tid = threadIdx.x;
    const int n0  = blockIdx.x * 128;
    const int b   = n0 >> 12;
    const int hw0 = n0 & 4095;
    const float* xin = in + (size_t)b * CC * HWSZ + hw0;

    // coalesced x tile + cn/sc table
    for (int i = tid; i < DD * 128; i += 128) {
        int d = i >> 7, p = i & 127;
        xs[i] = xin[(size_t)d * HWSZ + p];
    }
    for (int i = tid; i < KK; i += 128) cnsc[i] = g_cnsc[i];
    __syncthreads();

    // per-pixel stats (exact ns per reference rounding) + int8 pack
    float ns = 0.f, xmax = 0.f, l1x = 0.f;
    #pragma unroll
    for (int d = 0; d < DD; d++) {
        float v = xs[d * 128 + tid];
        ns = __fadd_rn(ns, __fmul_rn(v, v));
        float a = fabsf(v);
        xmax = fmaxf(xmax, a);
        l1x += a;
    }
    const float sx   = 126.f / fmaxf(xmax, 1e-30f);
    const float rsx2 = -2.f / sx;
    uint32_t qx[16];
    #pragma unroll
    for (int w = 0; w < 16; w++) {
        uint32_t pk = 0;
        #pragma unroll
        for (int j = 0; j < 4; j++) {
            int q = __float2int_rn(xs[(w * 4 + j) * 128 + tid] * sx);
            pk |= ((uint32_t)(q & 0xFF)) << (j * 8);
        }
        qx[w] = pk;
    }

    // guaranteed-containment margin (errors: eps_x*L1c + eps_c*L1(x_hat))
    const float epsx   = 0.5f / sx;
    const float l1cmax = __int_as_float(g_l1cmax_i);
    const float epsc   = __int_as_float(g_cmaxmax_i) / 252.f;
    const float M = 2.5f * (epsx * l1cmax + epsc * (l1x + 64.f * epsx)) + 2e-4f;

    // streaming coarse min + candidate slots
    float m = 3.4e38f;
    float ss[NSLOT];
    int   sn[NSLOT];
    #pragma unroll
    for (int i = 0; i < NSLOT; i++) { ss[i] = 3.4e38f; sn[i] = 0; }
    bool ovf = false;

    const uint4* qcp = (const uint4*)g_qc;   // [KK][4]
    #pragma unroll 2
    for (int n = 0; n < KK; n += 2) {
        uint4 c0 = __ldg(&qcp[n * 4 + 0]);
        uint4 c1 = __ldg(&qcp[n * 4 + 1]);
        uint4 c2 = __ldg(&qcp[n * 4 + 2]);
        uint4 c3 = __ldg(&qcp[n * 4 + 3]);
        uint4 e0 = __ldg(&qcp[n * 4 + 4]);
        uint4 e1 = __ldg(&qcp[n * 4 + 5]);
        uint4 e2 = __ldg(&qcp[n * 4 + 6]);
        uint4 e3 = __ldg(&qcp[n * 4 + 7]);

        int a0 = 0, a1 = 0, a2 = 0, a3 = 0;
        int b0 = 0, b1 = 0, b2 = 0, b3 = 0;
        a0 = __dp4a((int)qx[0],  (int)c0.x, a0);
        a1 = __dp4a((int)qx[1],  (int)c0.y, a1);
        a2 = __dp4a((int)qx[2],  (int)c0.z, a2);
        a3 = __dp4a((int)qx[3],  (int)c0.w, a3);
        a0 = __dp4a((int)qx[4],  (int)c1.x, a0);
        a1 = __dp4a((int)qx[5],  (int)c1.y, a1);
        a2 = __dp4a((int)qx[6],  (int)c1.z, a2);
        a3 = __dp4a((int)qx[7],  (int)c1.w, a3);
        a0 = __dp4a((int)qx[8],  (int)c2.x, a0);
        a1 = __dp4a((int)qx[9],  (int)c2.y, a1);
        a2 = __dp4a((int)qx[10], (int)c2.z, a2);
        a3 = __dp4a((int)qx[11], (int)c2.w, a3);
        a0 = __dp4a((int)qx[12], (int)c3.x, a0);
        a1 = __dp4a((int)qx[13], (int)c3.y, a1);
        a2 = __dp4a((int)qx[14], (int)c3.z, a2);
        a3 = __dp4a((int)qx[15], (int)c3.w, a3);

        b0 = __dp4a((int)qx[0],  (int)e0.x, b0);
        b1 = __dp4a((int)qx[1],  (int)e0.y, b1);
        b2 = __dp4a((int)qx[2],  (int)e0.z, b2);
        b3 = __dp4a((int)qx[3],  (int)e0.w, b3);
        b0 = __dp4a((int)qx[4],  (int)e1.x, b0);
        b1 = __dp4a((int)qx[5],  (int)e1.y, b1);
        b2 = __dp4a((int)qx[6],  (int)e1.z, b2);
        b3 = __dp4a((int)qx[7],  (int)e1.w, b3);
        b0 = __dp4a((int)qx[8],  (int)e2.x, b0);
        b1 = __dp4a((int)qx[9],  (int)e2.y, b1);
        b2 = __dp4a((int)qx[10], (int)e2.z, b2);
        b3 = __dp4a((int)qx[11], (int)e2.w, b3);
        b0 = __dp4a((int)qx[12], (int)e3.x, b0);
        b1 = __dp4a((int)qx[13], (int)e3.y, b1);
        b2 = __dp4a((int)qx[14], (int)e3.z, b2);
        b3 = __dp4a((int)qx[15], (int)e3.w, b3);

        int   dot0 = (a0 + a1) + (a2 + a3);
        int   dot1 = (b0 + b1) + (b2 + b3);
        float2 cs0 = cnsc[n];
        float2 cs1 = cnsc[n + 1];
        float s0 = fmaf(rsx2, __int2float_rn(dot0) * cs0.y, cs0.x);
        float s1 = fmaf(rsx2, __int2float_rn(dot1) * cs1.y, cs1.x);

        m = fminf(m, s0);
        if (s0 <= m + M) {
            float thr = m + M;
            bool placed = false;
            #pragma unroll
            for (int i = 0; i < NSLOT; i++)
                if (!placed && ss[i] > thr) { ss[i] = s0; sn[i] = n; placed = true; }
            if (!placed) ovf = true;
        }
        m = fminf(m, s1);
        if (s1 <= m + M) {
            float thr = m + M;
            bool placed = false;
            #pragma unroll
            for (int i = 0; i < NSLOT; i++)
                if (!placed && ss[i] > thr) { ss[i] = s1; sn[i] = n + 1; placed = true; }
            if (!placed) ovf = true;
        }
    }

    // exact refine (reference-rounding fp32; u64 key => first-index tiebreak)
    unsigned long long best = ~0ull;
    const float thrF = m + M;
    if (ovf) {
        for (int n = 0; n < KK; n++) {
            const float4* cr = (const float4*)(cb + (size_t)n * DD);
            float acc = 0.f;
            #pragma unroll
            for (int w = 0; w < 16; w++) {
                float4 c = __ldg(&cr[w]);
                acc = __fmaf_rn(xs[(w * 4 + 0) * 128 + tid], c.x, acc);
                acc = __fmaf_rn(xs[(w * 4 + 1) * 128 + tid], c.y, acc);
                acc = __fmaf_rn(xs[(w * 4 + 2) * 128 + tid], c.z, acc);
                acc = __fmaf_rn(xs[(w * 4 + 3) * 128 + tid], c.w, acc);
            }
            float sE = __fsub_rn(__fadd_rn(ns, cnsc[n].x), __fmul_rn(2.f, acc));
            unsigned long long key =
                ((unsigned long long)__float_as_uint(sE) << 32) | (unsigned)n;
            if (key < best) best = key;
        }
    } else {
        #pragma unroll
        for (int i = 0; i < NSLOT; i++) {
            if (ss[i] <= thrF) {
                int n = sn[i];
                const float4* cr = (const float4*)(cb + (size_t)n * DD);
                float acc = 0.f;
                #pragma unroll
                for (int w = 0; w < 16; w++) {
                    float4 c = __ldg(&cr[w]);
                    acc = __fmaf_rn(xs[(w * 4 + 0) * 128 + tid], c.x, acc);
                    acc = __fmaf_rn(xs[(w * 4 + 1) * 128 + tid], c.y, acc);
                    acc = __fmaf_rn(xs[(w * 4 + 2) * 128 + tid], c.z, acc);
                    acc = __fmaf_rn(xs[(w * 4 + 3) * 128 + tid], c.w, acc);
                }
                float sE = __fsub_rn(__fadd_rn(ns, cnsc[n].x), __fmul_rn(2.f, acc));
                unsigned long long key =
                    ((unsigned long long)__float_as_uint(sE) << 32) | (unsigned)n;
                if (key < best) best = key;
            }
        }
    }

    int bidx = (int)(best & 0xffffffffull);
    g_idx[n0 + tid] = bidx;
    atomicAdd(&g_counts[bidx], 1.0f);   // integer-valued float sum: deterministic
}

// ---------------------------------------------------------------------------
// Kernel 3: gather quantized output + per-block loss partial.
// Loads vectorized; outq = out+1 (4 mod 16) so stores stay scalar.
// ---------------------------------------------------------------------------
__global__ void gather_loss_kernel(const float* __restrict__ in,
                                   const float* __restrict__ cb,
                                   float* __restrict__ outq) {
    const int tid = threadIdx.x;
    const int e   = (blockIdx.x * 256 + tid) * 4;

    int b  = e >> 18;
    int r  = e & 262143;
    int c  = r >> 12;
    int hw = r & 4095;           // multiple of 4
    const int4 gi = *(const int4*)&g_idx[(b << 12) | hw];

    float4 x = *(const float4*)(in + e);
    float q0 = __ldg(&cb[gi.x * DD + c]);
    float q1 = __ldg(&cb[gi.y * DD + c]);
    float q2 = __ldg(&cb[gi.z * DD + c]);
    float q3 = __ldg(&cb[gi.w * DD + c]);

    float d0 = q0 - x.x, d1 = q1 - x.y, d2 = q2 - x.z, d3 = q3 - x.w;
    outq[e + 0] = x.x + d0;
    outq[e + 1] = x.y + d1;
    outq[e + 2] = x.z + d2;
    outq[e + 3] = x.w + d3;
    float part = d0 * d0 + d1 * d1 + d2 * d2 + d3 * d3;

    #pragma unroll
    for (int o2 = 16; o2; o2 >>= 1)
        part += __shfl_xor_sync(0xffffffffu, part, o2);
    __shared__ float ws[8];
    if ((tid & 31) == 0) ws[tid >> 5] = part;
    __syncthreads();
    if (tid == 0) {
        float s = 0.f;
        #pragma unroll
        for (int w = 0; w < 8; w++) s += ws[w];
        g_part[blockIdx.x] = s;
    }
}

// ---------------------------------------------------------------------------
// Kernel 4: finalize loss + perplexity
// ---------------------------------------------------------------------------
__global__ void finalize_kernel(const float* __restrict__ beta,
                                float* __restrict__ loss_out,
                                float* __restrict__ pp_out) {
    const int t = threadIdx.x;   // 1024

    float ls = 0.f;
    #pragma unroll
    for (int i = 0; i < GATHER_BLOCKS / 1024; i++)
        ls += g_part[t * (GATHER_BLOCKS / 1024) + i];

    float em  = g_counts[t] * (1.0f / (float)NPIX);
    float ent = em * logf(em + 1e-10f);

    #pragma unroll
    for (int o = 16; o; o >>= 1) {
        ls  += __shfl_xor_sync(0xffffffffu, ls, o);
        ent += __shfl_xor_sync(0xffffffffu, ent, o);
    }
    __shared__ float wl[32], we[32];
    if ((t & 31) == 0) { wl[t >> 5] = ls; we[t >> 5] = ent; }
    __syncthreads();
    if (t == 0) {
        float tl = 0.f, te = 0.f;
        #pragma unroll
        for (int w = 0; w < 32; w++) { tl += wl[w]; te += we[w]; }
        float mean = tl / (float)NEL;
        *loss_out = (1.0f + *beta) * 10.0f * mean;   // KLD_SCALE = 10
        *pp_out   = expf(-te);
    }
}

// ---------------------------------------------------------------------------
// Launch
// ---------------------------------------------------------------------------
extern "C" void kernel_launch(void* const* d_in, const int* in_sizes, int n_in,
                              void* d_out, int out_size) {
    const float* in   = nullptr;
    const float* cb   = nullptr;
    const float* beta = nullptr;
    for (int i = 0; i < n_in; i++) {
        if      (in_sizes[i] == NEL)     in   = (const float*)d_in[i];
        else if (in_sizes[i] == KK * DD) cb   = (const float*)d_in[i];
        else if (in_sizes[i] == 1)       beta = (const float*)d_in[i];
    }

    float* out      = (float*)d_out;
    float* loss_out = out;
    float* q_out    = out + 1;
    float* pp_out   = out + (out_size - 1);

    prep_kernel<<<(KK + 255) / 256, 256>>>(cb);
    argmin_kernel<<<NPIX / 128, 128>>>(in, cb);
    gather_loss_kernel<<<GATHER_BLOCKS, 256>>>(in, cb, q_out);
    finalize_kernel<<<1, 1024>>>(beta, loss_out, pp_out);
}